// round 3
// baseline (speedup 1.0000x reference)
#include <cuda_runtime.h>

// Reference computes per-row loss but only loss[-1] survives the Python loop.
// => Compute everything for row (bs-1) only. nt = 2048, bs = 4096 (fixed shapes).
//
// Inputs (metadata order):
//  0 prior_mu, 1 prior_sigma, 2 mu, 3 sigma, 4 target_y, 5 eps_post, 6 eps_prior
// Output: scalar float.

#define NT      2048
#define THREADS 1024
#define ELEMS   (NT / THREADS)   // 2

__device__ __forceinline__ float warp_max(float v) {
    #pragma unroll
    for (int o = 16; o > 0; o >>= 1) v = fmaxf(v, __shfl_xor_sync(0xffffffffu, v, o));
    return v;
}
__device__ __forceinline__ float warp_sum(float v) {
    #pragma unroll
    for (int o = 16; o > 0; o >>= 1) v += __shfl_xor_sync(0xffffffffu, v, o);
    return v;
}

__global__ __launch_bounds__(THREADS, 1)
void criterion_last_row_kernel(
    const float* __restrict__ prior_mu,
    const float* __restrict__ prior_sigma,
    const float* __restrict__ mu,
    const float* __restrict__ sigma,
    const float* __restrict__ target_y,
    const float* __restrict__ eps_post,
    const float* __restrict__ eps_prior,
    float* __restrict__ out,
    long long row_off)
{
    __shared__ float s_a[32];
    __shared__ float s_b[32];
    __shared__ float s_c[32];

    const int t    = threadIdx.x;
    const int lane = t & 31;
    const int warp = t >> 5;

    // ---- Load row elements; compute z's and the per-element Gaussian terms ----
    float zpost[ELEMS], zprior[ELEMS];
    float logsig_sum = 0.0f;
    float quad_sum   = 0.0f;

    #pragma unroll
    for (int i = 0; i < ELEMS; i++) {
        const long long idx = row_off + t + i * THREADS;
        const float m  = mu[idx];
        const float s  = sigma[idx];
        const float pm = prior_mu[idx];
        const float ps = prior_sigma[idx];
        const float ep = eps_post[idx];
        const float er = eps_prior[idx];
        const float y  = target_y[idx];

        zpost[i]  = fmaf(sqrtf(s),  ep, m);
        zprior[i] = fmaf(sqrtf(ps), er, pm);

        const float d = y - m;
        logsig_sum += logf(s);
        quad_sum   += d * d / s;
    }

    // ---- Phase 1: block max of z_post and z_prior ----
    float mx_q = fmaxf(zpost[0],  zpost[1]);
    float mx_p = fmaxf(zprior[0], zprior[1]);
    mx_q = warp_max(mx_q);
    mx_p = warp_max(mx_p);
    if (lane == 0) { s_a[warp] = mx_q; s_b[warp] = mx_p; }
    __syncthreads();
    if (warp == 0) {
        float a = s_a[lane];
        float b = s_b[lane];
        a = warp_max(a);
        b = warp_max(b);
        if (lane == 0) { s_a[0] = a; s_b[0] = b; }
    }
    __syncthreads();
    mx_q = s_a[0];
    mx_p = s_b[0];
    __syncthreads();   // protect smem reuse below

    // ---- Phase 2: block sum of exp(z - max) for both ----
    float se_q = 0.0f, se_p = 0.0f;
    #pragma unroll
    for (int i = 0; i < ELEMS; i++) {
        se_q += expf(zpost[i]  - mx_q);
        se_p += expf(zprior[i] - mx_p);
    }
    se_q = warp_sum(se_q);
    se_p = warp_sum(se_p);
    if (lane == 0) { s_a[warp] = se_q; s_b[warp] = se_p; }
    __syncthreads();
    if (warp == 0) {
        float a = s_a[lane];
        float b = s_b[lane];
        a = warp_sum(a);
        b = warp_sum(b);
        if (lane == 0) { s_a[0] = a; s_b[0] = b; }
    }
    __syncthreads();
    const float lse_q = logf(s_a[0]);   // log-sum-exp denominators
    const float lse_p = logf(s_b[0]);
    __syncthreads();

    // ---- Phase 3: KL terms + final three sums ----
    float kl_sum = 0.0f;
    #pragma unroll
    for (int i = 0; i < ELEMS; i++) {
        const float lq = zpost[i]  - mx_q - lse_q;   // log_softmax(z_post)
        const float lp = zprior[i] - mx_p - lse_p;   // log_softmax(z_prior)
        kl_sum += expf(lp) * (lp - lq);
    }
    kl_sum     = warp_sum(kl_sum);
    logsig_sum = warp_sum(logsig_sum);
    quad_sum   = warp_sum(quad_sum);
    if (lane == 0) { s_a[warp] = kl_sum; s_b[warp] = logsig_sum; s_c[warp] = quad_sum; }
    __syncthreads();
    if (warp == 0) {
        float a = s_a[lane];
        float b = s_b[lane];
        float c = s_c[lane];
        a = warp_sum(a);
        b = warp_sum(b);
        c = warp_sum(c);
        if (lane == 0) {
            const float LOG_2PI = 1.8378770664093453f;
            const float log_prob = -0.5f * ((float)NT * LOG_2PI + b + c);
            const float kl = a / (float)NT;
            out[0] = -(log_prob / (float)NT - kl);
        }
    }
}

extern "C" void kernel_launch(void* const* d_in, const int* in_sizes, int n_in,
                              void* d_out, int out_size)
{
    const float* prior_mu    = (const float*)d_in[0];
    const float* prior_sigma = (const float*)d_in[1];
    const float* mu          = (const float*)d_in[2];
    const float* sigma       = (const float*)d_in[3];
    const float* target_y    = (const float*)d_in[4];
    const float* eps_post    = (const float*)d_in[5];
    const float* eps_prior   = (const float*)d_in[6];

    // Only the last row matters: offset = total_elems - nt
    const long long total   = (long long)in_sizes[0];
    const long long row_off = total - (long long)NT;

    criterion_last_row_kernel<<<1, THREADS>>>(
        prior_mu, prior_sigma, mu, sigma, target_y, eps_post, eps_prior,
        (float*)d_out, row_off);
}

// round 4
// speedup vs baseline: 1.2105x; 1.2105x over previous
#include <cuda_runtime.h>

// Only loss[-1] survives the reference's Python loop => compute row (bs-1) only.
// nt = 2048. Single CTA, 1024 threads, 2 elems/thread via float2.
// Single-pass online-softmax reduction:
//   state_q = (m_q, s_q)            for lse(z_post)
//   state_p = (m_p, s_p, w)         for lse(z_prior) and w = sum e^{zp-m_p}(zp-zq)
//   kl_sum  = w/s_p + lse_q - lse_p          (since sum p = 1)
// plus plain sums: logsig, quad.

#define NT      2048
#define THREADS 1024
#define NWARP   (THREADS / 32)

__global__ __launch_bounds__(THREADS, 1)
void criterion_last_row_kernel(
    const float2* __restrict__ prior_mu,
    const float2* __restrict__ prior_sigma,
    const float2* __restrict__ mu,
    const float2* __restrict__ sigma,
    const float2* __restrict__ target_y,
    const float2* __restrict__ eps_post,
    const float2* __restrict__ eps_prior,
    float* __restrict__ out,
    long long off2)            // float2 offset of the last row
{
    __shared__ float sm[7][NWARP];

    const int t    = threadIdx.x;
    const int lane = t & 31;
    const int warp = t >> 5;
    const long long idx = off2 + t;

    // ---- One load wave (7 x LDG.64, fully MLP-overlapped) ----
    const float2 m  = mu[idx];
    const float2 s  = sigma[idx];
    const float2 pm = prior_mu[idx];
    const float2 ps = prior_sigma[idx];
    const float2 y  = target_y[idx];
    const float2 ep = eps_post[idx];
    const float2 er = eps_prior[idx];

    // ---- Per-thread local values ----
    const float zq0 = fmaf(sqrtf(s.x),  ep.x, m.x);
    const float zq1 = fmaf(sqrtf(s.y),  ep.y, m.y);
    const float zp0 = fmaf(sqrtf(ps.x), er.x, pm.x);
    const float zp1 = fmaf(sqrtf(ps.y), er.y, pm.y);

    float logsig = __logf(s.x * s.y);                 // log s0 + log s1, range-safe
    const float d0 = y.x - m.x;
    const float d1 = y.y - m.y;
    float quad = __fdividef(d0 * d0, s.x) + __fdividef(d1 * d1, s.y);

    // thread-local online-softmax states (exact for 2 elements)
    float mq = fmaxf(zq0, zq1);
    float sq = __expf(zq0 - mq) + __expf(zq1 - mq);

    float mp = fmaxf(zp0, zp1);
    const float e0 = __expf(zp0 - mp);
    const float e1 = __expf(zp1 - mp);
    float sp = e0 + e1;
    float w  = e0 * (zp0 - zq0) + e1 * (zp1 - zq1);

    // ---- Warp combine (online softmax merge + plain sums), 5 steps ----
    #pragma unroll
    for (int o = 16; o > 0; o >>= 1) {
        const float mq2 = __shfl_xor_sync(0xffffffffu, mq, o);
        const float sq2 = __shfl_xor_sync(0xffffffffu, sq, o);
        const float mp2 = __shfl_xor_sync(0xffffffffu, mp, o);
        const float sp2 = __shfl_xor_sync(0xffffffffu, sp, o);
        const float w2  = __shfl_xor_sync(0xffffffffu, w,  o);
        logsig += __shfl_xor_sync(0xffffffffu, logsig, o);
        quad   += __shfl_xor_sync(0xffffffffu, quad,   o);

        const float Mq = fmaxf(mq, mq2);
        sq = fmaf(sq, __expf(mq - Mq), sq2 * __expf(mq2 - Mq));
        mq = Mq;

        const float Mp = fmaxf(mp, mp2);
        const float a = __expf(mp - Mp);
        const float b = __expf(mp2 - Mp);
        sp = fmaf(sp, a, sp2 * b);
        w  = fmaf(w,  a, w2  * b);
        mp = Mp;
    }

    if (lane == 0) {
        sm[0][warp] = mq; sm[1][warp] = sq;
        sm[2][warp] = mp; sm[3][warp] = sp; sm[4][warp] = w;
        sm[5][warp] = logsig; sm[6][warp] = quad;
    }
    __syncthreads();

    // ---- Warp 0 combines the NWARP (=32) partials ----
    if (warp == 0) {
        mq = sm[0][lane]; sq = sm[1][lane];
        mp = sm[2][lane]; sp = sm[3][lane]; w = sm[4][lane];
        logsig = sm[5][lane]; quad = sm[6][lane];

        #pragma unroll
        for (int o = 16; o > 0; o >>= 1) {
            const float mq2 = __shfl_xor_sync(0xffffffffu, mq, o);
            const float sq2 = __shfl_xor_sync(0xffffffffu, sq, o);
            const float mp2 = __shfl_xor_sync(0xffffffffu, mp, o);
            const float sp2 = __shfl_xor_sync(0xffffffffu, sp, o);
            const float w2  = __shfl_xor_sync(0xffffffffu, w,  o);
            logsig += __shfl_xor_sync(0xffffffffu, logsig, o);
            quad   += __shfl_xor_sync(0xffffffffu, quad,   o);

            const float Mq = fmaxf(mq, mq2);
            sq = fmaf(sq, __expf(mq - Mq), sq2 * __expf(mq2 - Mq));
            mq = Mq;

            const float Mp = fmaxf(mp, mp2);
            const float a = __expf(mp - Mp);
            const float b = __expf(mp2 - Mp);
            sp = fmaf(sp, a, sp2 * b);
            w  = fmaf(w,  a, w2  * b);
            mp = Mp;
        }

        if (lane == 0) {
            const float LOG_2PI = 1.8378770664093453f;
            const float lse_q = mq + __logf(sq);
            const float lse_p = mp + __logf(sp);
            const float kl = (__fdividef(w, sp) + lse_q - lse_p) * (1.0f / (float)NT);
            const float log_prob = -0.5f * ((float)NT * LOG_2PI + logsig + quad);
            out[0] = -(log_prob * (1.0f / (float)NT) - kl);
        }
    }
}

extern "C" void kernel_launch(void* const* d_in, const int* in_sizes, int n_in,
                              void* d_out, int out_size)
{
    const long long total   = (long long)in_sizes[0];
    const long long off2    = (total - (long long)NT) / 2;   // row is 2048-aligned

    criterion_last_row_kernel<<<1, THREADS>>>(
        (const float2*)d_in[0], (const float2*)d_in[1],
        (const float2*)d_in[2], (const float2*)d_in[3],
        (const float2*)d_in[4], (const float2*)d_in[5],
        (const float2*)d_in[6],
        (float*)d_out, off2);
}